// round 13
// baseline (speedup 1.0000x reference)
#include <cuda_runtime.h>

// ---------------------------------------------------------------------------
// Model_19095424598065 v13 : algebraically reduced graph-spectral net.
// vs v12 (committed 554us): occupancy 2 -> 3 CTAs/SM via register diet:
//   - __launch_bounds__(256, 3)  (<=85 regs)
//   - mode_gemm in two passes of 4 tiles (halves accumulator+staging regs;
//     M re-read is L2-hot)
//   - stages C/E read F from smem per node as ulonglong2 (consecutive-float
//     pairs ARE f32x2 operands -> zero packing MOVs), freeing Fr registers
// ---------------------------------------------------------------------------

typedef unsigned long long u64t;

#define NT 256
#define TT 8

__device__ float d_M0[8 * 128 * 128];   // scalar layout [k][i][c]
__device__ float d_M2[8 * 128 * 128];
__device__ float d_tv[8];
__device__ float d_b1[128];
__device__ float d_b3[128];

// ------------------------------ helpers ------------------------------------
static __device__ __forceinline__ u64t dup2(float x) {
    u64t r; asm("mov.b64 %0, {%1, %1};" : "=l"(r) : "f"(x)); return r;
}
static __device__ __forceinline__ u64t pack2(float a, float b) {
    u64t r; asm("mov.b64 %0, {%1, %2};" : "=l"(r) : "f"(a), "f"(b)); return r;
}
static __device__ __forceinline__ void unpack2(u64t v, float& a, float& b) {
    asm("mov.b64 {%0, %1}, %2;" : "=f"(a), "=f"(b) : "l"(v));
}
static __device__ __forceinline__ void fma2(u64t& d, u64t a, u64t b) {
    asm("fma.rn.f32x2 %0, %1, %2, %3;" : "=l"(d) : "l"(a), "l"(b), "l"(d));
}
static __device__ __forceinline__ u64t add2(u64t a, u64t b) {
    u64t r; asm("add.rn.f32x2 %0, %1, %2;" : "=l"(r) : "l"(a), "l"(b)); return r;
}

// --------------------------- fused precompute ------------------------------
__global__ void pre_kernel(const float* __restrict__ U, const float* __restrict__ adj,
                           const float* __restrict__ w0, const float* __restrict__ w2,
                           const float* __restrict__ Ws1, const float* __restrict__ Wn1,
                           const float* __restrict__ Ws3, const float* __restrict__ Wn3,
                           const float* __restrict__ bs1, const float* __restrict__ bn1,
                           const float* __restrict__ bs3, const float* __restrict__ bn3)
{
    __shared__ float sw[1024];
    __shared__ float spart[128];
    __shared__ float slam[8];
    const int b = blockIdx.x, c = threadIdx.x;
    const int which = b >> 7, i = b & 127;
    const float* w  = which ? w2  : w0;
    const float* Ws = which ? Ws3 : Ws1;
    const float* Wn = which ? Wn3 : Wn1;

    {
        const int k = c >> 4, s = c & 15;
        float part = 0.f;
        for (int n = s; n < 64; n += 16) {
            float g = 0.f;
            for (int m = 0; m < 64; m++) g += adj[n * 64 + m] * U[m * 64 + k];
            part += U[n * 64 + k] * g;
        }
        spart[c] = part;
    }
    for (int idx = c; idx < 1024; idx += 128) sw[idx] = w[i * 1024 + idx];
    __syncthreads();
    if (c < 8) {
        float lam = 0.f;
        for (int s = 0; s < 16; s++) lam += spart[c * 16 + s];
        slam[c] = lam;
    }
    if (b == 0) {
        if (c < 128) { d_b1[c] = bs1[c] + bn1[c]; d_b3[c] = bs3[c] + bn3[c]; }
        if (c < 8) {
            float ts = 0.f;
            for (int n = 0; n < 64; n++) ts += U[n * 64 + c];
            d_tv[c] = ts;
        }
    }
    __syncthreads();

    float lam[8], acc[8];
#pragma unroll
    for (int k = 0; k < 8; k++) { lam[k] = slam[k]; acc[k] = 0.f; }
#pragma unroll 2
    for (int j = 0; j < 128; j++) {
        float ws = __ldg(Ws + j * 128 + c);
        float wn = __ldg(Wn + j * 128 + c);
#pragma unroll
        for (int k = 0; k < 8; k++)
            acc[k] += sw[j * 8 + k] * fmaf(lam[k], wn, ws);
    }
    float* M = which ? d_M2 : d_M0;
#pragma unroll
    for (int k = 0; k < 8; k++) M[(k * 128 + i) * 128 + c] = acc[k];
}

// ------------------------------- main kernel -------------------------------
// smem (floats):
//  sFX  [0    , 8192 )  XF/F in place [t][k][c]
//  sUm  [8192 , 8704 )  Um[n][k] stride 8
//  sWp  [8704 , 9728 )  Wp[p][c]
//  sV   [9728 , 10752)  bp|b1|b3|g1|be1|g3|be3|bo(8)|tv(8)
//  sY   [10752, 11264)  stage-A y[t][k][p]
//  sWoB [11264, 12288)  Wo pairs, per-lane swizzled (512 u64)
#define O_FX  0
#define O_UM  8192
#define O_WP  8704
#define O_V   9728
#define O_Y   10752
#define O_WOB 11264
#define SMEMF 12288

// F[t,k,:] = XF[t,k,:] @ M_k (K=128), in place. Warp k owns mode k's rows.
// Two passes of 4 tiles each to halve accumulator/staging registers.
static __device__ __forceinline__ void mode_gemm(const float* __restrict__ M,
                                                 float* sFX, int tid)
{
    const int k = tid >> 5, lane = tid & 31;
    const float4* Mk4 = (const float4*)(M + k * 16384);

#pragma unroll 1
    for (int hh = 0; hh < 2; hh++) {
        u64t a01[4], a23[4];
#pragma unroll
        for (int t = 0; t < 4; t++) { a01[t] = 0ull; a23[t] = 0ull; }

#pragma unroll 2
        for (int i4 = 0; i4 < 32; i4++) {
            float4 xv[4];
#pragma unroll
            for (int t = 0; t < 4; t++)  // uniform address -> broadcast, 1 wf
                xv[t] = *(const float4*)(sFX + ((4 * hh + t) * 8 + k) * 128 + 4 * i4);
#pragma unroll
            for (int ii = 0; ii < 4; ii++) {
                float4 m = __ldg(&Mk4[(4 * i4 + ii) * 32 + lane]);
                u64t m01 = pack2(m.x, m.y), m23 = pack2(m.z, m.w);
#pragma unroll
                for (int t = 0; t < 4; t++) {
                    float xs = (ii == 0) ? xv[t].x : (ii == 1) ? xv[t].y
                             : (ii == 2) ? xv[t].z : xv[t].w;
                    u64t xb = dup2(xs);
                    fma2(a01[t], xb, m01);
                    fma2(a23[t], xb, m23);
                }
            }
        }
#pragma unroll
        for (int t = 0; t < 4; t++) {
            ulonglong2 fv; fv.x = a01[t]; fv.y = a23[t];
            *(ulonglong2*)(sFX + ((4 * hh + t) * 8 + k) * 128 + 4 * lane) = fv;
        }
    }
}

// Stage C, one warp = one tile t: o = Um@F + b1 -> LN -> relu -> xf2 = Um^T h.
// F read from smem per node (ulonglong2 = ready f32x2 operands, no Fr regs).
static __device__ __forceinline__ void tile_stageC(float* sFX, const float* sUm,
                                                   const float* sV, int t, int lane)
{
    const float4 bq = *(const float4*)(sV + 128 + 4 * lane);
    const float4 gq = *(const float4*)(sV + 384 + 4 * lane);
    const float4 eq = *(const float4*)(sV + 512 + 4 * lane);
    const u64t b01 = pack2(bq.x, bq.y), b23 = pack2(bq.z, bq.w);
    const float* Fb = sFX + t * 1024 + 4 * lane;

    u64t X20[8], X21[8];
#pragma unroll
    for (int k = 0; k < 8; k++) { X20[k] = 0ull; X21[k] = 0ull; }

#pragma unroll 2
    for (int n = 0; n < 64; n++) {
        float4 u0 = *(const float4*)(sUm + n * 8);      // uniform -> broadcast
        float4 u1 = *(const float4*)(sUm + n * 8 + 4);
        u64t uk[8] = {dup2(u0.x), dup2(u0.y), dup2(u0.z), dup2(u0.w),
                      dup2(u1.x), dup2(u1.y), dup2(u1.z), dup2(u1.w)};
        u64t o0 = b01, o1 = b23;
#pragma unroll
        for (int k = 0; k < 8; k++) {
            ulonglong2 fv = *(const ulonglong2*)(Fb + k * 128);
            fma2(o0, uk[k], fv.x); fma2(o1, uk[k], fv.y);
        }
        float a, b, c, d;
        unpack2(o0, a, b); unpack2(o1, c, d);
        float s = a + b + c + d;
        float s2 = a * a + b * b + c * c + d * d;
#pragma unroll
        for (int m = 1; m < 32; m <<= 1) {
            s  += __shfl_xor_sync(0xffffffffu, s, m);
            s2 += __shfl_xor_sync(0xffffffffu, s2, m);
        }
        const float mu = s * 0.0078125f;
        const float rstd = rsqrtf(s2 * 0.0078125f - mu * mu + 1e-5f);
        u64t hA = pack2(fmaxf((a - mu) * rstd * gq.x + eq.x, 0.f),
                        fmaxf((b - mu) * rstd * gq.y + eq.y, 0.f));
        u64t hB = pack2(fmaxf((c - mu) * rstd * gq.z + eq.z, 0.f),
                        fmaxf((d - mu) * rstd * gq.w + eq.w, 0.f));
#pragma unroll
        for (int k = 0; k < 8; k++) { fma2(X20[k], uk[k], hA); fma2(X21[k], uk[k], hB); }
    }
#pragma unroll
    for (int k = 0; k < 8; k++) {
        ulonglong2 xo; xo.x = X20[k]; xo.y = X21[k];
        *(ulonglong2*)(sFX + (t * 8 + k) * 128 + 4 * lane) = xo;
    }
}

// Stage E, one warp = one tile: o = Um@F + b3 -> LN -> relu -> out = h@Wo + bo.
// F from smem per node; Wo stays in per-lane registers (swizzled load).
static __device__ __forceinline__ void tile_stageE(const float* sFX, const float* sUm,
                                                   const float* sV, const u64t* sWoB,
                                                   float* __restrict__ outg,
                                                   int t, int lane)
{
    const float4 bq = *(const float4*)(sV + 256 + 4 * lane);
    const float4 gq = *(const float4*)(sV + 640 + 4 * lane);
    const float4 eq = *(const float4*)(sV + 768 + 4 * lane);
    const u64t b01 = pack2(bq.x, bq.y), b23 = pack2(bq.z, bq.w);
    const float* Fb = sFX + t * 1024 + 4 * lane;

    u64t w2[4][4];
    {
        const int l7 = lane & 7;
#pragma unroll
        for (int u = 0; u < 8; u++) {
            int p = lane * 8 + (u ^ l7);
            u64t A = sWoB[2 * p], B = sWoB[2 * p + 1];
            const int j = u >> 1, qb = (u & 1) * 2;
            w2[j][qb] = A; w2[j][qb + 1] = B;
        }
    }
    const int g = lane >> 3;
    float2 boP = *(const float2*)(sV + 896 + 2 * g);

#pragma unroll 2
    for (int n = 0; n < 64; n++) {
        float4 u0 = *(const float4*)(sUm + n * 8);
        float4 u1 = *(const float4*)(sUm + n * 8 + 4);
        u64t uk[8] = {dup2(u0.x), dup2(u0.y), dup2(u0.z), dup2(u0.w),
                      dup2(u1.x), dup2(u1.y), dup2(u1.z), dup2(u1.w)};
        u64t o0 = b01, o1 = b23;
#pragma unroll
        for (int k = 0; k < 8; k++) {
            ulonglong2 fv = *(const ulonglong2*)(Fb + k * 128);
            fma2(o0, uk[k], fv.x); fma2(o1, uk[k], fv.y);
        }
        float a, b, c, d;
        unpack2(o0, a, b); unpack2(o1, c, d);
        float s = a + b + c + d;
        float s2 = a * a + b * b + c * c + d * d;
#pragma unroll
        for (int m = 1; m < 32; m <<= 1) {
            s  += __shfl_xor_sync(0xffffffffu, s, m);
            s2 += __shfl_xor_sync(0xffffffffu, s2, m);
        }
        const float mu = s * 0.0078125f;
        const float rstd = rsqrtf(s2 * 0.0078125f - mu * mu + 1e-5f);
        float h0 = fmaxf((a - mu) * rstd * gq.x + eq.x, 0.f);
        float h1 = fmaxf((b - mu) * rstd * gq.y + eq.y, 0.f);
        float h2 = fmaxf((c - mu) * rstd * gq.z + eq.z, 0.f);
        float h3 = fmaxf((d - mu) * rstd * gq.w + eq.w, 0.f);

        u64t acc2[4] = {0ull, 0ull, 0ull, 0ull};
        u64t hb;
        hb = dup2(h0);
#pragma unroll
        for (int q = 0; q < 4; q++) fma2(acc2[q], hb, w2[0][q]);
        hb = dup2(h1);
#pragma unroll
        for (int q = 0; q < 4; q++) fma2(acc2[q], hb, w2[1][q]);
        hb = dup2(h2);
#pragma unroll
        for (int q = 0; q < 4; q++) fma2(acc2[q], hb, w2[2][q]);
        hb = dup2(h3);
#pragma unroll
        for (int q = 0; q < 4; q++) fma2(acc2[q], hb, w2[3][q]);

#pragma unroll
        for (int q = 0; q < 4; q++)
            acc2[q] = add2(acc2[q], __shfl_xor_sync(0xffffffffu, acc2[q], 16));
#pragma unroll
        for (int q = 0; q < 4; q++)
            acc2[q] = add2(acc2[q], __shfl_xor_sync(0xffffffffu, acc2[q], 8));
        u64t v = (g == 0) ? acc2[0] : (g == 1) ? acc2[1] : (g == 2) ? acc2[2] : acc2[3];
        v = add2(v, __shfl_xor_sync(0xffffffffu, v, 4));
        v = add2(v, __shfl_xor_sync(0xffffffffu, v, 2));
        v = add2(v, __shfl_xor_sync(0xffffffffu, v, 1));
        if ((lane & 7) == (n & 7)) {
            float x, y; unpack2(v, x, y);
            *(float2*)(outg + n * 8 + 2 * g) = make_float2(x + boP.x, y + boP.y);
        }
    }
}

__global__ void __launch_bounds__(NT, 3)
main_kernel(const float* __restrict__ x, const float* __restrict__ U,
            const float* __restrict__ Wp, const float* __restrict__ bp,
            const float* __restrict__ g1, const float* __restrict__ be1,
            const float* __restrict__ g3, const float* __restrict__ be3,
            const float* __restrict__ Wo, const float* __restrict__ bo,
            float* __restrict__ out)
{
    extern __shared__ float sm[];
    float* sFX  = sm + O_FX;
    float* sUm  = sm + O_UM;
    float* sWp  = sm + O_WP;
    float* sV   = sm + O_V;
    float* sY   = sm + O_Y;
    u64t*  sWoB = (u64t*)(sm + O_WOB);

    const int tid = threadIdx.x;
    const int wid = tid >> 5, lane = tid & 31;

    // ---- init: weights/vectors ----
    if (tid < 64) {
#pragma unroll
        for (int k = 0; k < 8; k++) sUm[tid * 8 + k] = U[tid * 64 + k];
    }
    for (int i = tid; i < 1024; i += NT) sWp[i] = Wp[i];
    if (tid < 128) {
        sV[tid]       = bp[tid];
        sV[128 + tid] = d_b1[tid];
        sV[256 + tid] = d_b3[tid];
        sV[384 + tid] = g1[tid];
        sV[512 + tid] = be1[tid];
        sV[640 + tid] = g3[tid];
        sV[768 + tid] = be3[tid];
    }
    if (tid < 8) { sV[896 + tid] = bo[tid]; sV[904 + tid] = d_tv[tid]; }
    if (tid < 256) {
        const int l = tid >> 3, u = (tid & 7) ^ (l & 7);
        const int j = u >> 1, qb = (u & 1) * 2;
        const int c = 4 * l + j;
        sWoB[2 * tid]     = pack2(Wo[c * 8 + 2 * qb],     Wo[c * 8 + 2 * qb + 1]);
        sWoB[2 * tid + 1] = pack2(Wo[c * 8 + 2 * qb + 2], Wo[c * 8 + 2 * qb + 3]);
    }
    __syncthreads();

    // ---- stage A pass 1: y[t][k][p] = sum_n Um[n,k] x[t][n][p] ----
    {
        const int k = lane >> 2, q = lane & 3;
        const float2* xg2 = (const float2*)(x + (size_t)blockIdx.x * 4096 + wid * 512);
        u64t acc = 0ull;
#pragma unroll 4
        for (int n = 0; n < 64; n++) {
            float um = sUm[n * 8 + k];
            float2 xv = __ldg(&xg2[n * 4 + q]);
            fma2(acc, dup2(um), pack2(xv.x, xv.y));
        }
        float a, b; unpack2(acc, a, b);
        *(float2*)(sY + wid * 64 + k * 8 + 2 * q) = make_float2(a, b);
    }
    __syncthreads();

    // ---- stage A pass 2: XF[t][k][c] = tv[k]*bp[c] + sum_p y[t][k][p] Wp[p][c] ----
    // warp k writes rows (t,k) -> consumed by the same warp in mode_gemm (no sync)
    {
        const int k = wid, c4 = lane;
        const float tvk = sV[904 + k];
        const float4 bp4 = ((const float4*)sV)[c4];
#pragma unroll
        for (int t = 0; t < TT; t++) {
            const float* yv = sY + t * 64 + k * 8;
            u64t a01 = 0ull, a23 = 0ull;
            u64t tb = dup2(tvk);
            fma2(a01, tb, pack2(bp4.x, bp4.y));
            fma2(a23, tb, pack2(bp4.z, bp4.w));
#pragma unroll
            for (int p = 0; p < 8; p++) {
                u64t yb = dup2(yv[p]);
                float4 wp = ((const float4*)(sWp + p * 128))[c4];
                fma2(a01, yb, pack2(wp.x, wp.y));
                fma2(a23, yb, pack2(wp.z, wp.w));
            }
            float a, b, c, d;
            unpack2(a01, a, b); unpack2(a23, c, d);
            *(float4*)(sFX + (t * 8 + k) * 128 + 4 * c4) = make_float4(a, b, c, d);
        }
    }

    // ---- stage B: f0 = per-mode GEMM with M0 (in place) ----
    mode_gemm(d_M0, sFX, tid);
    __syncthreads();

    // ---- stage C: warp w handles tile w entirely ----
    tile_stageC(sFX, sUm, sV, wid, lane);
    __syncthreads();

    // ---- stage D: f2 = per-mode GEMM with M2 (in place) ----
    mode_gemm(d_M2, sFX, tid);
    __syncthreads();

    // ---- stage E: warp w handles tile w entirely, fused output projection ----
    float* outg = out + (size_t)blockIdx.x * 4096;
    tile_stageE(sFX, sUm, sV, sWoB, outg + wid * 512, wid, lane);
}

// ------------------------------- launch ------------------------------------

extern "C" void kernel_launch(void* const* d_in, const int* in_sizes, int n_in,
                              void* d_out, int out_size)
{
    const float* x   = (const float*)d_in[0];
    const float* adj = (const float*)d_in[1];
    const float* U   = (const float*)d_in[2];
    const float* Wp  = (const float*)d_in[3];
    const float* bp  = (const float*)d_in[4];
    const float* w0  = (const float*)d_in[5];
    const float* w2  = (const float*)d_in[6];
    const float* Ws1 = (const float*)d_in[7];
    const float* bs1 = (const float*)d_in[8];
    const float* Wn1 = (const float*)d_in[9];
    const float* bn1 = (const float*)d_in[10];
    const float* g1  = (const float*)d_in[11];
    const float* be1 = (const float*)d_in[12];
    const float* Ws3 = (const float*)d_in[13];
    const float* bs3 = (const float*)d_in[14];
    const float* Wn3 = (const float*)d_in[15];
    const float* bn3 = (const float*)d_in[16];
    const float* g3  = (const float*)d_in[17];
    const float* be3 = (const float*)d_in[18];
    const float* Wo  = (const float*)d_in[19];
    const float* bo  = (const float*)d_in[20];
    float* out = (float*)d_out;

    pre_kernel<<<256, 128>>>(U, adj, w0, w2, Ws1, Wn1, Ws3, Wn3,
                             bs1, bn1, bs3, bn3);

    const size_t smem = SMEMF * sizeof(float);  // 48 KB -> 3 CTAs/SM
    cudaFuncSetAttribute(main_kernel, cudaFuncAttributeMaxDynamicSharedMemorySize,
                         (int)smem);
    main_kernel<<<2048, NT, smem>>>(x, U, Wp, bp, g1, be1, g3, be3, Wo, bo, out);
}

// round 14
// speedup vs baseline: 1.4329x; 1.4329x over previous
#include <cuda_runtime.h>

// ---------------------------------------------------------------------------
// Model_19095424598065 v14 : algebraically reduced graph-spectral net.
// CONSOLIDATION (= v12 byte-for-byte, the measured optimum at 554.0us):
//   - R4 main kernel exactly: per-mode f32x2 GEMMs on precomputed
//     M_k = w_k(Ws + lam_k Wn), tile-per-warp LN stages, fused output proj.
//   - fused single pre_kernel (bench-vs-kernel gap ~4us).
// Ledger: 9/9 hand-modifications to the v4 inner loops regressed
// (issue-count, layout, and occupancy directions all measured worse).
// ---------------------------------------------------------------------------

typedef unsigned long long u64t;

#define NT 256
#define TT 8

__device__ float d_M0[8 * 128 * 128];   // scalar layout [k][i][c]
__device__ float d_M2[8 * 128 * 128];
__device__ float d_tv[8];
__device__ float d_b1[128];
__device__ float d_b3[128];

// ------------------------------ helpers ------------------------------------
static __device__ __forceinline__ u64t dup2(float x) {
    u64t r; asm("mov.b64 %0, {%1, %1};" : "=l"(r) : "f"(x)); return r;
}
static __device__ __forceinline__ u64t pack2(float a, float b) {
    u64t r; asm("mov.b64 %0, {%1, %2};" : "=l"(r) : "f"(a), "f"(b)); return r;
}
static __device__ __forceinline__ void unpack2(u64t v, float& a, float& b) {
    asm("mov.b64 {%0, %1}, %2;" : "=f"(a), "=f"(b) : "l"(v));
}
static __device__ __forceinline__ void fma2(u64t& d, u64t a, u64t b) {
    asm("fma.rn.f32x2 %0, %1, %2, %3;" : "=l"(d) : "l"(a), "l"(b), "l"(d));
}
static __device__ __forceinline__ u64t add2(u64t a, u64t b) {
    u64t r; asm("add.rn.f32x2 %0, %1, %2;" : "=l"(r) : "l"(a), "l"(b)); return r;
}

// --------------------------- fused precompute ------------------------------
// 256 blocks: b<128 -> M0 row b; b>=128 -> M2 row b-128. lam computed locally.
__global__ void pre_kernel(const float* __restrict__ U, const float* __restrict__ adj,
                           const float* __restrict__ w0, const float* __restrict__ w2,
                           const float* __restrict__ Ws1, const float* __restrict__ Wn1,
                           const float* __restrict__ Ws3, const float* __restrict__ Wn3,
                           const float* __restrict__ bs1, const float* __restrict__ bn1,
                           const float* __restrict__ bs3, const float* __restrict__ bn3)
{
    __shared__ float sw[1024];
    __shared__ float spart[128];
    __shared__ float slam[8];
    const int b = blockIdx.x, c = threadIdx.x;
    const int which = b >> 7, i = b & 127;
    const float* w  = which ? w2  : w0;
    const float* Ws = which ? Ws3 : Ws1;
    const float* Wn = which ? Wn3 : Wn1;

    {
        const int k = c >> 4, s = c & 15;
        float part = 0.f;
        for (int n = s; n < 64; n += 16) {
            float g = 0.f;
            for (int m = 0; m < 64; m++) g += adj[n * 64 + m] * U[m * 64 + k];
            part += U[n * 64 + k] * g;
        }
        spart[c] = part;
    }
    for (int idx = c; idx < 1024; idx += 128) sw[idx] = w[i * 1024 + idx];
    __syncthreads();
    if (c < 8) {
        float lam = 0.f;
        for (int s = 0; s < 16; s++) lam += spart[c * 16 + s];
        slam[c] = lam;
    }
    if (b == 0) {
        if (c < 128) { d_b1[c] = bs1[c] + bn1[c]; d_b3[c] = bs3[c] + bn3[c]; }
        if (c < 8) {
            float ts = 0.f;
            for (int n = 0; n < 64; n++) ts += U[n * 64 + c];
            d_tv[c] = ts;
        }
    }
    __syncthreads();

    float lam[8], acc[8];
#pragma unroll
    for (int k = 0; k < 8; k++) { lam[k] = slam[k]; acc[k] = 0.f; }
#pragma unroll 2
    for (int j = 0; j < 128; j++) {
        float ws = __ldg(Ws + j * 128 + c);
        float wn = __ldg(Wn + j * 128 + c);
#pragma unroll
        for (int k = 0; k < 8; k++)
            acc[k] += sw[j * 8 + k] * fmaf(lam[k], wn, ws);
    }
    float* M = which ? d_M2 : d_M0;
#pragma unroll
    for (int k = 0; k < 8; k++) M[(k * 128 + i) * 128 + c] = acc[k];
}

// ------------------------------- main kernel (R4 verbatim) -----------------
// smem (floats):
//  sFX  [0    , 8192 )  XF/F in place [t][k][c]
//  sUm  [8192 , 8704 )  Um[n][k] stride 8
//  sWp  [8704 , 9728 )  Wp[p][c]
//  sV   [9728 , 10752)  bp|b1|b3|g1|be1|g3|be3|bo(8)|tv(8)
//  sY   [10752, 11264)  stage-A y[t][k][p]
//  sWoB [11264, 12288)  Wo pairs, per-lane swizzled (512 u64)
#define O_FX  0
#define O_UM  8192
#define O_WP  8704
#define O_V   9728
#define O_Y   10752
#define O_WOB 11264
#define SMEMF 12288

// F[t,k,:] = XF[t,k,:] @ M_k (K=128), in place. Warp k owns mode k's rows.
static __device__ __forceinline__ void mode_gemm(const float* __restrict__ M,
                                                 float* sFX, int tid)
{
    const int k = tid >> 5, lane = tid & 31;
    const float4* Mk4 = (const float4*)(M + k * 16384);
    u64t a01[TT], a23[TT];
#pragma unroll
    for (int t = 0; t < TT; t++) { a01[t] = 0ull; a23[t] = 0ull; }

#pragma unroll 2
    for (int i4 = 0; i4 < 32; i4++) {
        float4 xv[TT];
#pragma unroll
        for (int t = 0; t < TT; t++)  // uniform address -> broadcast, 1 wf
            xv[t] = *(const float4*)(sFX + (t * 8 + k) * 128 + 4 * i4);
#pragma unroll
        for (int ii = 0; ii < 4; ii++) {
            float4 m = __ldg(&Mk4[(4 * i4 + ii) * 32 + lane]);
            u64t m01 = pack2(m.x, m.y), m23 = pack2(m.z, m.w);
#pragma unroll
            for (int t = 0; t < TT; t++) {
                float xs = (ii == 0) ? xv[t].x : (ii == 1) ? xv[t].y
                         : (ii == 2) ? xv[t].z : xv[t].w;
                u64t xb = dup2(xs);
                fma2(a01[t], xb, m01);
                fma2(a23[t], xb, m23);
            }
        }
    }
#pragma unroll
    for (int t = 0; t < TT; t++) {
        float a, b, c, d;
        unpack2(a01[t], a, b); unpack2(a23[t], c, d);
        *(float4*)(sFX + (t * 8 + k) * 128 + 4 * lane) = make_float4(a, b, c, d);
    }
}

// Stage C, one warp = one tile t: o = Um@F + b1 -> LN -> relu -> xf2 = Um^T h,
// xf2 accumulated in registers, written back into sFX rows (t,k).
static __device__ __forceinline__ void tile_stageC(float* sFX, const float* sUm,
                                                   const float* sV, int t, int lane)
{
    u64t Fr0[8], Fr1[8];
#pragma unroll
    for (int k = 0; k < 8; k++) {
        float4 f = *(const float4*)(sFX + (t * 8 + k) * 128 + 4 * lane);
        Fr0[k] = pack2(f.x, f.y); Fr1[k] = pack2(f.z, f.w);
    }
    const float4 bq = *(const float4*)(sV + 128 + 4 * lane);
    const float4 gq = *(const float4*)(sV + 384 + 4 * lane);
    const float4 eq = *(const float4*)(sV + 512 + 4 * lane);
    const u64t b01 = pack2(bq.x, bq.y), b23 = pack2(bq.z, bq.w);

    u64t X20[8], X21[8];
#pragma unroll
    for (int k = 0; k < 8; k++) { X20[k] = 0ull; X21[k] = 0ull; }

#pragma unroll 4
    for (int n = 0; n < 64; n++) {
        float4 u0 = *(const float4*)(sUm + n * 8);      // uniform -> broadcast
        float4 u1 = *(const float4*)(sUm + n * 8 + 4);
        u64t uk[8] = {dup2(u0.x), dup2(u0.y), dup2(u0.z), dup2(u0.w),
                      dup2(u1.x), dup2(u1.y), dup2(u1.z), dup2(u1.w)};
        u64t o0 = b01, o1 = b23;
#pragma unroll
        for (int k = 0; k < 8; k++) { fma2(o0, uk[k], Fr0[k]); fma2(o1, uk[k], Fr1[k]); }
        float a, b, c, d;
        unpack2(o0, a, b); unpack2(o1, c, d);
        float s = a + b + c + d;
        float s2 = a * a + b * b + c * c + d * d;
#pragma unroll
        for (int m = 1; m < 32; m <<= 1) {
            s  += __shfl_xor_sync(0xffffffffu, s, m);
            s2 += __shfl_xor_sync(0xffffffffu, s2, m);
        }
        const float mu = s * 0.0078125f;
        const float rstd = rsqrtf(s2 * 0.0078125f - mu * mu + 1e-5f);
        u64t hA = pack2(fmaxf((a - mu) * rstd * gq.x + eq.x, 0.f),
                        fmaxf((b - mu) * rstd * gq.y + eq.y, 0.f));
        u64t hB = pack2(fmaxf((c - mu) * rstd * gq.z + eq.z, 0.f),
                        fmaxf((d - mu) * rstd * gq.w + eq.w, 0.f));
#pragma unroll
        for (int k = 0; k < 8; k++) { fma2(X20[k], uk[k], hA); fma2(X21[k], uk[k], hB); }
    }
#pragma unroll
    for (int k = 0; k < 8; k++) {
        float a, b, c, d;
        unpack2(X20[k], a, b); unpack2(X21[k], c, d);
        *(float4*)(sFX + (t * 8 + k) * 128 + 4 * lane) = make_float4(a, b, c, d);
    }
}

// Stage E, one warp = one tile: o = Um@F + b3 -> LN -> relu -> out = h@Wo + bo.
// Wo held in per-lane registers (swizzled smem load); butterfly reductions;
// 2-lane predicated STG per node.
static __device__ __forceinline__ void tile_stageE(const float* sFX, const float* sUm,
                                                   const float* sV, const u64t* sWoB,
                                                   float* __restrict__ outg,
                                                   int t, int lane)
{
    u64t Fr0[8], Fr1[8];
#pragma unroll
    for (int k = 0; k < 8; k++) {
        float4 f = *(const float4*)(sFX + (t * 8 + k) * 128 + 4 * lane);
        Fr0[k] = pack2(f.x, f.y); Fr1[k] = pack2(f.z, f.w);
    }
    const float4 bq = *(const float4*)(sV + 256 + 4 * lane);
    const float4 gq = *(const float4*)(sV + 640 + 4 * lane);
    const float4 eq = *(const float4*)(sV + 768 + 4 * lane);
    const u64t b01 = pack2(bq.x, bq.y), b23 = pack2(bq.z, bq.w);

    u64t w2[4][4];
    {
        const int l7 = lane & 7;
#pragma unroll
        for (int u = 0; u < 8; u++) {
            int p = lane * 8 + (u ^ l7);
            u64t A = sWoB[2 * p], B = sWoB[2 * p + 1];
            const int j = u >> 1, qb = (u & 1) * 2;
            w2[j][qb] = A; w2[j][qb + 1] = B;
        }
    }
    const int g = lane >> 3;
    float2 boP = *(const float2*)(sV + 896 + 2 * g);

#pragma unroll 2
    for (int n = 0; n < 64; n++) {
        float4 u0 = *(const float4*)(sUm + n * 8);
        float4 u1 = *(const float4*)(sUm + n * 8 + 4);
        u64t uk[8] = {dup2(u0.x), dup2(u0.y), dup2(u0.z), dup2(u0.w),
                      dup2(u1.x), dup2(u1.y), dup2(u1.z), dup2(u1.w)};
        u64t o0 = b01, o1 = b23;
#pragma unroll
        for (int k = 0; k < 8; k++) { fma2(o0, uk[k], Fr0[k]); fma2(o1, uk[k], Fr1[k]); }
        float a, b, c, d;
        unpack2(o0, a, b); unpack2(o1, c, d);
        float s = a + b + c + d;
        float s2 = a * a + b * b + c * c + d * d;
#pragma unroll
        for (int m = 1; m < 32; m <<= 1) {
            s  += __shfl_xor_sync(0xffffffffu, s, m);
            s2 += __shfl_xor_sync(0xffffffffu, s2, m);
        }
        const float mu = s * 0.0078125f;
        const float rstd = rsqrtf(s2 * 0.0078125f - mu * mu + 1e-5f);
        float h0 = fmaxf((a - mu) * rstd * gq.x + eq.x, 0.f);
        float h1 = fmaxf((b - mu) * rstd * gq.y + eq.y, 0.f);
        float h2 = fmaxf((c - mu) * rstd * gq.z + eq.z, 0.f);
        float h3 = fmaxf((d - mu) * rstd * gq.w + eq.w, 0.f);

        u64t acc2[4] = {0ull, 0ull, 0ull, 0ull};
        u64t hb;
        hb = dup2(h0);
#pragma unroll
        for (int q = 0; q < 4; q++) fma2(acc2[q], hb, w2[0][q]);
        hb = dup2(h1);
#pragma unroll
        for (int q = 0; q < 4; q++) fma2(acc2[q], hb, w2[1][q]);
        hb = dup2(h2);
#pragma unroll
        for (int q = 0; q < 4; q++) fma2(acc2[q], hb, w2[2][q]);
        hb = dup2(h3);
#pragma unroll
        for (int q = 0; q < 4; q++) fma2(acc2[q], hb, w2[3][q]);

#pragma unroll
        for (int q = 0; q < 4; q++)
            acc2[q] = add2(acc2[q], __shfl_xor_sync(0xffffffffu, acc2[q], 16));
#pragma unroll
        for (int q = 0; q < 4; q++)
            acc2[q] = add2(acc2[q], __shfl_xor_sync(0xffffffffu, acc2[q], 8));
        u64t v = (g == 0) ? acc2[0] : (g == 1) ? acc2[1] : (g == 2) ? acc2[2] : acc2[3];
        v = add2(v, __shfl_xor_sync(0xffffffffu, v, 4));
        v = add2(v, __shfl_xor_sync(0xffffffffu, v, 2));
        v = add2(v, __shfl_xor_sync(0xffffffffu, v, 1));
        if ((lane & 7) == (n & 7)) {
            float x, y; unpack2(v, x, y);
            *(float2*)(outg + n * 8 + 2 * g) = make_float2(x + boP.x, y + boP.y);
        }
    }
}

__global__ void __launch_bounds__(NT, 2)
main_kernel(const float* __restrict__ x, const float* __restrict__ U,
            const float* __restrict__ Wp, const float* __restrict__ bp,
            const float* __restrict__ g1, const float* __restrict__ be1,
            const float* __restrict__ g3, const float* __restrict__ be3,
            const float* __restrict__ Wo, const float* __restrict__ bo,
            float* __restrict__ out)
{
    extern __shared__ float sm[];
    float* sFX  = sm + O_FX;
    float* sUm  = sm + O_UM;
    float* sWp  = sm + O_WP;
    float* sV   = sm + O_V;
    float* sY   = sm + O_Y;
    u64t*  sWoB = (u64t*)(sm + O_WOB);

    const int tid = threadIdx.x;
    const int wid = tid >> 5, lane = tid & 31;

    // ---- init: weights/vectors ----
    if (tid < 64) {
#pragma unroll
        for (int k = 0; k < 8; k++) sUm[tid * 8 + k] = U[tid * 64 + k];
    }
    for (int i = tid; i < 1024; i += NT) sWp[i] = Wp[i];
    if (tid < 128) {
        sV[tid]       = bp[tid];
        sV[128 + tid] = d_b1[tid];
        sV[256 + tid] = d_b3[tid];
        sV[384 + tid] = g1[tid];
        sV[512 + tid] = be1[tid];
        sV[640 + tid] = g3[tid];
        sV[768 + tid] = be3[tid];
    }
    if (tid < 8) { sV[896 + tid] = bo[tid]; sV[904 + tid] = d_tv[tid]; }
    if (tid < 256) {
        const int l = tid >> 3, u = (tid & 7) ^ (l & 7);
        const int j = u >> 1, qb = (u & 1) * 2;
        const int c = 4 * l + j;
        sWoB[2 * tid]     = pack2(Wo[c * 8 + 2 * qb],     Wo[c * 8 + 2 * qb + 1]);
        sWoB[2 * tid + 1] = pack2(Wo[c * 8 + 2 * qb + 2], Wo[c * 8 + 2 * qb + 3]);
    }
    __syncthreads();

    // ---- stage A pass 1: y[t][k][p] = sum_n Um[n,k] x[t][n][p] ----
    {
        const int k = lane >> 2, q = lane & 3;
        const float2* xg2 = (const float2*)(x + (size_t)blockIdx.x * 4096 + wid * 512);
        u64t acc = 0ull;
#pragma unroll 4
        for (int n = 0; n < 64; n++) {
            float um = sUm[n * 8 + k];
            float2 xv = __ldg(&xg2[n * 4 + q]);
            fma2(acc, dup2(um), pack2(xv.x, xv.y));
        }
        float a, b; unpack2(acc, a, b);
        *(float2*)(sY + wid * 64 + k * 8 + 2 * q) = make_float2(a, b);
    }
    __syncthreads();

    // ---- stage A pass 2: XF[t][k][c] = tv[k]*bp[c] + sum_p y[t][k][p] Wp[p][c] ----
    // warp k writes rows (t,k) -> consumed by the same warp in mode_gemm (no sync)
    {
        const int k = wid, c4 = lane;
        const float tvk = sV[904 + k];
        const float4 bp4 = ((const float4*)sV)[c4];
#pragma unroll
        for (int t = 0; t < TT; t++) {
            const float* yv = sY + t * 64 + k * 8;
            u64t a01 = 0ull, a23 = 0ull;
            u64t tb = dup2(tvk);
            fma2(a01, tb, pack2(bp4.x, bp4.y));
            fma2(a23, tb, pack2(bp4.z, bp4.w));
#pragma unroll
            for (int p = 0; p < 8; p++) {
                u64t yb = dup2(yv[p]);
                float4 wp = ((const float4*)(sWp + p * 128))[c4];
                fma2(a01, yb, pack2(wp.x, wp.y));
                fma2(a23, yb, pack2(wp.z, wp.w));
            }
            float a, b, c, d;
            unpack2(a01, a, b); unpack2(a23, c, d);
            *(float4*)(sFX + (t * 8 + k) * 128 + 4 * c4) = make_float4(a, b, c, d);
        }
    }

    // ---- stage B: f0 = per-mode GEMM with M0 (in place) ----
    mode_gemm(d_M0, sFX, tid);
    __syncthreads();

    // ---- stage C: warp w handles tile w entirely ----
    tile_stageC(sFX, sUm, sV, wid, lane);
    __syncthreads();

    // ---- stage D: f2 = per-mode GEMM with M2 (in place) ----
    mode_gemm(d_M2, sFX, tid);
    __syncthreads();

    // ---- stage E: warp w handles tile w entirely, fused output projection ----
    float* outg = out + (size_t)blockIdx.x * 4096;
    tile_stageE(sFX, sUm, sV, sWoB, outg + wid * 512, wid, lane);
}

// ------------------------------- launch ------------------------------------

extern "C" void kernel_launch(void* const* d_in, const int* in_sizes, int n_in,
                              void* d_out, int out_size)
{
    const float* x   = (const float*)d_in[0];
    const float* adj = (const float*)d_in[1];
    const float* U   = (const float*)d_in[2];
    const float* Wp  = (const float*)d_in[3];
    const float* bp  = (const float*)d_in[4];
    const float* w0  = (const float*)d_in[5];
    const float* w2  = (const float*)d_in[6];
    const float* Ws1 = (const float*)d_in[7];
    const float* bs1 = (const float*)d_in[8];
    const float* Wn1 = (const float*)d_in[9];
    const float* bn1 = (const float*)d_in[10];
    const float* g1  = (const float*)d_in[11];
    const float* be1 = (const float*)d_in[12];
    const float* Ws3 = (const float*)d_in[13];
    const float* bs3 = (const float*)d_in[14];
    const float* Wn3 = (const float*)d_in[15];
    const float* bn3 = (const float*)d_in[16];
    const float* g3  = (const float*)d_in[17];
    const float* be3 = (const float*)d_in[18];
    const float* Wo  = (const float*)d_in[19];
    const float* bo  = (const float*)d_in[20];
    float* out = (float*)d_out;

    pre_kernel<<<256, 128>>>(U, adj, w0, w2, Ws1, Wn1, Ws3, Wn3,
                             bs1, bn1, bs3, bn3);

    const size_t smem = SMEMF * sizeof(float);  // 48 KB -> 2 CTAs/SM
    cudaFuncSetAttribute(main_kernel, cudaFuncAttributeMaxDynamicSharedMemorySize,
                         (int)smem);
    main_kernel<<<2048, NT, smem>>>(x, U, Wp, bp, g1, be1, g3, be3, Wo, bo, out);
}